// round 13
// baseline (speedup 1.0000x reference)
#include <cuda_runtime.h>
#include <cuda_bf16.h>
#include <cstdint>

#define Bz   64
#define Lz   1024
#define Hz   512
#define HALFz 256
#define Vz   32000
#define Mz   (Bz*Lz)          /* 65536 rows */
#define NCH  16               /* chunks of 64 steps */

typedef unsigned long long ull;

// ---------------- f32x2 packed-math helpers ----------------------------------
__device__ __forceinline__ void fma2(ull &d, ull a, ull b) {
    asm("fma.rn.f32x2 %0, %1, %2, %0;" : "+l"(d) : "l"(a), "l"(b));
}
__device__ __forceinline__ ull pk(float lo, float hi) {
    ull r; asm("mov.b64 %0, {%1, %2};" : "=l"(r) : "f"(lo), "f"(hi)); return r;
}
__device__ __forceinline__ float2 upk(ull v) {
    float2 r; asm("mov.b64 {%0, %1}, %2;" : "=f"(r.x), "=f"(r.y) : "l"(v)); return r;
}

// ---------------- warp-mma helpers -------------------------------------------
__device__ __forceinline__ uint32_t smem_u32(const void* p) {
    uint32_t a;
    asm("{ .reg .u64 t; cvta.to.shared.u64 t, %1; cvt.u32.u64 %0, t; }"
        : "=r"(a) : "l"(p));
    return a;
}
__device__ __forceinline__ void ldm4(uint32_t* r, uint32_t addr) {
    asm volatile("ldmatrix.sync.aligned.m8n8.x4.shared.b16 {%0,%1,%2,%3}, [%4];"
        : "=r"(r[0]), "=r"(r[1]), "=r"(r[2]), "=r"(r[3]) : "r"(addr));
}
__device__ __forceinline__ void mma_bf16(float* c, const uint32_t* a,
                                         const uint32_t* b) {
    asm volatile("mma.sync.aligned.m16n8k16.row.col.f32.bf16.bf16.f32 "
        "{%0,%1,%2,%3}, {%4,%5,%6,%7}, {%8,%9}, {%0,%1,%2,%3};"
        : "+f"(c[0]), "+f"(c[1]), "+f"(c[2]), "+f"(c[3])
        : "r"(a[0]), "r"(a[1]), "r"(a[2]), "r"(a[3]), "r"(b[0]), "r"(b[1]));
}
__device__ __forceinline__ void cpa16(uint32_t dst, const void* src) {
    asm volatile("cp.async.ca.shared.global [%0], [%1], 16;"
                 :: "r"(dst), "l"(src) : "memory");
}
__device__ __forceinline__ void cpa_wait_all() {
    asm volatile("cp.async.wait_all;" ::: "memory");
}

// ---------------- scratch ----------------------------------------------------
__device__ float g_x   [(size_t)Mz * Hz];
__device__ float g_ks  [(size_t)Mz * HALFz];
__device__ float g_ke  [(size_t)Mz * HALFz];
__device__ float g_sinv[2 * Mz];
__device__ float g_gram[(size_t)2 * Bz * NCH * 64 * 64];
__device__ float g_c   [Bz * 2 * HALFz];
// bf16 hi/lo activations
__device__ __nv_bfloat16 g_embhi[(size_t)Vz * Hz], g_emblo[(size_t)Vz * Hz];
__device__ __nv_bfloat16 g_r1hi[(size_t)Mz * 1024], g_r1lo[(size_t)Mz * 1024];
__device__ __nv_bfloat16 g_hhi [(size_t)Mz * Hz],   g_hlo [(size_t)Mz * Hz];
// bf16 hi/lo weights [N][K]
__device__ __nv_bfloat16 g_w1hi[1024 * 512], g_w1lo[1024 * 512];
__device__ __nv_bfloat16 g_w2hi[512 * 1024], g_w2lo[512 * 1024];
__device__ __nv_bfloat16 g_swhi[256 * 512],  g_swlo[256 * 512];
__device__ __nv_bfloat16 g_ewhi[256 * 512],  g_ewlo[256 * 512];

// ---------------- elementwise fp32 -> bf16 hi/lo split -----------------------
__global__ __launch_bounds__(256)
void esplit_k(const float* __restrict__ E, __nv_bfloat16* __restrict__ hi,
              __nv_bfloat16* __restrict__ lo, int n4)
{
    int i = blockIdx.x * 256 + threadIdx.x;
    if (i >= n4) return;
    float4 v = *(const float4*)(E + (size_t)i * 4);
    __nv_bfloat162 h01 = __floats2bfloat162_rn(v.x, v.y);
    __nv_bfloat162 h23 = __floats2bfloat162_rn(v.z, v.w);
    __nv_bfloat162 l01 = __floats2bfloat162_rn(
        v.x - __bfloat162float(h01.x), v.y - __bfloat162float(h01.y));
    __nv_bfloat162 l23 = __floats2bfloat162_rn(
        v.z - __bfloat162float(h23.x), v.w - __bfloat162float(h23.y));
    *(uint2*)(hi + (size_t)i * 4) = make_uint2(*(uint32_t*)&h01, *(uint32_t*)&h23);
    *(uint2*)(lo + (size_t)i * 4) = make_uint2(*(uint32_t*)&l01, *(uint32_t*)&l23);
}

// ---------------- weight transpose + bf16 split:  W[K][N] -> [N][K] hi/lo ----
__global__ __launch_bounds__(256)
void wsplit_k(const float* __restrict__ W, __nv_bfloat16* __restrict__ hi,
              __nv_bfloat16* __restrict__ lo, int K, int N)
{
    __shared__ float t[32][33];
    const int n0 = blockIdx.x * 32, k0 = blockIdx.y * 32;
    const int tx = threadIdx.x & 31, ty = threadIdx.x >> 5;
    #pragma unroll
    for (int p = 0; p < 4; p++) {
        int kk = ty + p * 8;
        t[kk][tx] = W[(size_t)(k0 + kk) * N + n0 + tx];
    }
    __syncthreads();
    #pragma unroll
    for (int p = 0; p < 4; p++) {
        int r = ty + p * 8;
        float v = t[tx][r];
        __nv_bfloat16 h = __float2bfloat16(v);
        __nv_bfloat16 l = __float2bfloat16(v - __bfloat162float(h));
        size_t o = (size_t)(n0 + r) * K + k0 + tx;
        hi[o] = h; lo[o] = l;
    }
}

// ---------------- HMMA split-bf16 GEMM (pure cp.async mainloop) --------------
// 128x128 block, BK=32, 8 warps (4m x 2n), warp tile 32x64, m16n8k16.
// MODE 0: A gathered via seq (embed split), epi relu -> bf16 hi/lo out
// MODE 1: A direct,                         epi +bias+embed gather -> fp32
// MODE 2: A direct,                         epi +bias -> fp32
#define MG_STR  40
#define MG_AH   0
#define MG_AL   (128 * MG_STR)
#define MG_BH   (2 * 128 * MG_STR)
#define MG_BL   (3 * 128 * MG_STR)
#define MG_STAGE (4 * 128 * MG_STR)
#define MG_SMEM (2 * MG_STAGE * 2)

template<int MODE>
__global__ __launch_bounds__(256, 2)
void mgemm_k(const int* __restrict__ seq, const float* __restrict__ embed,
             const __nv_bfloat16* __restrict__ Ahi,
             const __nv_bfloat16* __restrict__ Alo,
             const __nv_bfloat16* __restrict__ Bhi,
             const __nv_bfloat16* __restrict__ Blo,
             const float* __restrict__ bias,
             float* __restrict__ CoutF,
             __nv_bfloat16* __restrict__ CoutHi,
             __nv_bfloat16* __restrict__ CoutLo,
             int Kfull, int Nfull)
{
    extern __shared__ __nv_bfloat16 smb[];
    __shared__ int seqs[128];

    const int tid  = threadIdx.x;
    const int lane = tid & 31;
    const int wid  = tid >> 5;
    const int wm   = wid & 3;
    const int wn   = wid >> 2;
    const int m0 = blockIdx.y * 128;
    const int n0 = blockIdx.x * 128;

    if (MODE != 2 && tid < 128) seqs[tid] = seq[m0 + tid];
    __syncthreads();

    float acc[2][8][4];
    #pragma unroll
    for (int i = 0; i < 2; i++)
        #pragma unroll
        for (int n = 0; n < 8; n++)
            #pragma unroll
            for (int q = 0; q < 4; q++) acc[i][n][q] = 0.f;

    const int nk = Kfull >> 5;

    auto mg_load = [&](int kc, int s) {
        const uint32_t sbu = smem_u32(smb + s * MG_STAGE);
        const int k0 = kc << 5;
        {   // A: 256 threads -> (row 0..127) x (buf hi/lo); 4x cpa16 each
            const int row = tid & 127;
            const int buf = tid >> 7;
            size_t rs = (size_t)(MODE == 0 ? seqs[row] : m0 + row) * Kfull + k0;
            const __nv_bfloat16* src = (buf ? Alo : Ahi) + rs;
            uint32_t dst = sbu + ((buf ? MG_AL : MG_AH) + row * MG_STR) * 2;
            cpa16(dst,      src);
            cpa16(dst + 16, src + 8);
            cpa16(dst + 32, src + 16);
            cpa16(dst + 48, src + 24);
        }
        {   // B
            const int row0 = tid >> 2;
            const int k8   = (tid & 3) << 3;
            #pragma unroll
            for (int p = 0; p < 2; p++) {
                int n = row0 + p * 64;
                size_t o = (size_t)(n0 + n) * Kfull + k0 + k8;
                uint32_t d = sbu + (n * MG_STR + k8) * 2;
                cpa16(d + MG_BH * 2, Bhi + o);
                cpa16(d + MG_BL * 2, Blo + o);
            }
        }
    };

    mg_load(0, 0);
    cpa_wait_all();
    __syncthreads();

    for (int kc = 0; kc < nk; kc++) {
        if (kc + 1 < nk) mg_load(kc + 1, (kc + 1) & 1);

        const __nv_bfloat16* sb = smb + (kc & 1) * MG_STAGE;
        const uint32_t aH = smem_u32(sb + MG_AH);
        const uint32_t aL = smem_u32(sb + MG_AL);
        const uint32_t bH = smem_u32(sb + MG_BH);
        const uint32_t bL = smem_u32(sb + MG_BL);

        #pragma unroll
        for (int ks = 0; ks < 2; ks++) {
            uint32_t ah[2][4], al[2][4];
            const int ar = wm * 32 + (lane & 15);
            const int ac = ks * 16 + ((lane >> 4) << 3);
            #pragma unroll
            for (int i = 0; i < 2; i++) {
                uint32_t off = ((ar + i * 16) * MG_STR + ac) * 2;
                ldm4(ah[i], aH + off);
                ldm4(al[i], aL + off);
            }
            #pragma unroll
            for (int j = 0; j < 4; j++) {
                const int nr = wn * 64 + j * 16 + (lane & 7) + ((lane >> 4) << 3);
                const int kc2 = ks * 16 + (((lane >> 3) & 1) << 3);
                uint32_t off = (nr * MG_STR + kc2) * 2;
                uint32_t bh[4], bl[4];
                ldm4(bh, bH + off);
                ldm4(bl, bL + off);
                #pragma unroll
                for (int i = 0; i < 2; i++) {
                    mma_bf16(acc[i][2 * j],     ah[i], bh);
                    mma_bf16(acc[i][2 * j + 1], ah[i], bh + 2);
                    mma_bf16(acc[i][2 * j],     ah[i], bl);
                    mma_bf16(acc[i][2 * j + 1], ah[i], bl + 2);
                    mma_bf16(acc[i][2 * j],     al[i], bh);
                    mma_bf16(acc[i][2 * j + 1], al[i], bh + 2);
                }
            }
        }
        cpa_wait_all();
        __syncthreads();
    }

    // epilogue
    #pragma unroll
    for (int i = 0; i < 2; i++) {
        int rlo = wm * 32 + i * 16 + (lane >> 2);
        #pragma unroll
        for (int n = 0; n < 8; n++) {
            int col = n0 + wn * 64 + n * 8 + (lane & 3) * 2;
            float b0 = bias[col], b1 = bias[col + 1];
            #pragma unroll
            for (int h = 0; h < 2; h++) {
                int rr = rlo + h * 8;
                size_t m = m0 + rr;
                float ox = acc[i][n][2 * h + 0] + b0;
                float oy = acc[i][n][2 * h + 1] + b1;
                if (MODE == 0) {
                    ox = fmaxf(ox, 0.f); oy = fmaxf(oy, 0.f);
                    __nv_bfloat162 hh = __floats2bfloat162_rn(ox, oy);
                    __nv_bfloat162 ll = __floats2bfloat162_rn(
                        ox - __bfloat162float(hh.x), oy - __bfloat162float(hh.y));
                    *(uint32_t*)(CoutHi + m * Nfull + col) = *(uint32_t*)&hh;
                    *(uint32_t*)(CoutLo + m * Nfull + col) = *(uint32_t*)&ll;
                } else {
                    if (MODE == 1) {
                        const float* e = embed + (size_t)seqs[rr] * Hz + col;
                        ox += e[0]; oy += e[1];
                    }
                    *(float2*)(CoutF + m * Nfull + col) = make_float2(ox, oy);
                }
            }
        }
    }
}

// ---------------- LayerNorm: g_x -> bf16 hi/lo h -----------------------------
__global__ __launch_bounds__(256)
void ln_k(const float* __restrict__ gam, const float* __restrict__ bet)
{
    int row  = blockIdx.x * 8 + (threadIdx.x >> 5);
    int lane = threadIdx.x & 31;
    const float* x = g_x + (size_t)row * Hz;

    float4 v[4];
    float sum = 0.f, sq = 0.f;
    #pragma unroll
    for (int i = 0; i < 4; i++) {
        v[i] = *(const float4*)(x + lane * 4 + i * 128);
        sum += v[i].x + v[i].y + v[i].z + v[i].w;
        sq  += v[i].x * v[i].x + v[i].y * v[i].y + v[i].z * v[i].z + v[i].w * v[i].w;
    }
    #pragma unroll
    for (int off = 16; off > 0; off >>= 1) {
        sum += __shfl_xor_sync(0xffffffffu, sum, off);
        sq  += __shfl_xor_sync(0xffffffffu, sq,  off);
    }
    float mean = sum * (1.f / 512.f);
    float var  = sq  * (1.f / 512.f) - mean * mean;
    float rs   = rsqrtf(var + 1e-5f);

    __nv_bfloat16* oh = g_hhi + (size_t)row * Hz;
    __nv_bfloat16* ol = g_hlo + (size_t)row * Hz;
    #pragma unroll
    for (int i = 0; i < 4; i++) {
        int col = lane * 4 + i * 128;
        float4 gg = *(const float4*)(gam + col);
        float4 bb = *(const float4*)(bet + col);
        float4 r;
        r.x = (v[i].x - mean) * rs * gg.x + bb.x;
        r.y = (v[i].y - mean) * rs * gg.y + bb.y;
        r.z = (v[i].z - mean) * rs * gg.z + bb.z;
        r.w = (v[i].w - mean) * rs * gg.w + bb.w;
        __nv_bfloat162 h01 = __floats2bfloat162_rn(r.x, r.y);
        __nv_bfloat162 h23 = __floats2bfloat162_rn(r.z, r.w);
        __nv_bfloat162 l01 = __floats2bfloat162_rn(
            r.x - __bfloat162float(h01.x), r.y - __bfloat162float(h01.y));
        __nv_bfloat162 l23 = __floats2bfloat162_rn(
            r.z - __bfloat162float(h23.x), r.w - __bfloat162float(h23.y));
        *(uint2*)(oh + col) = make_uint2(*(uint32_t*)&h01, *(uint32_t*)&h23);
        *(uint2*)(ol + col) = make_uint2(*(uint32_t*)&l01, *(uint32_t*)&l23);
    }
}

// ---------------- per-chunk Gram (fused 1/(k.k+eps) on the diagonal) ---------
__global__ __launch_bounds__(256)
void gram_k()
{
    __shared__ float Kh[64 * 129];
    const int ch = blockIdx.x, mat = blockIdx.y, b = blockIdx.z;
    const float* kbase = (mat ? g_ke : g_ks)
                         + (size_t)b * Lz * HALFz + (size_t)ch * 64 * HALFz;
    const int tid = threadIdx.x;
    const int t0 = (tid >> 4) * 4;
    const int s0 = (tid & 15) * 4;

    float acc[4][4];
    #pragma unroll
    for (int i = 0; i < 4; i++)
        #pragma unroll
        for (int q = 0; q < 4; q++) acc[i][q] = 0.f;

    const int row = tid >> 2;
    const int cb  = (tid & 3) * 32;

    for (int half = 0; half < 2; half++) {
        __syncthreads();
        #pragma unroll
        for (int d = 0; d < 8; d++) {
            float4 v = *(const float4*)(kbase + (size_t)row * HALFz + half * 128 + cb + 4 * d);
            float* w = Kh + row * 129 + cb + 4 * d;
            w[0] = v.x; w[1] = v.y; w[2] = v.z; w[3] = v.w;
        }
        __syncthreads();
        #pragma unroll 4
        for (int j = 0; j < 128; j++) {
            float a0 = Kh[(t0 + 0) * 129 + j], a1 = Kh[(t0 + 1) * 129 + j];
            float a2 = Kh[(t0 + 2) * 129 + j], a3 = Kh[(t0 + 3) * 129 + j];
            float b0 = Kh[(s0 + 0) * 129 + j], b1 = Kh[(s0 + 1) * 129 + j];
            float b2 = Kh[(s0 + 2) * 129 + j], b3 = Kh[(s0 + 3) * 129 + j];
            acc[0][0] += a0 * b0; acc[0][1] += a0 * b1; acc[0][2] += a0 * b2; acc[0][3] += a0 * b3;
            acc[1][0] += a1 * b0; acc[1][1] += a1 * b1; acc[1][2] += a1 * b2; acc[1][3] += a1 * b3;
            acc[2][0] += a2 * b0; acc[2][1] += a2 * b1; acc[2][2] += a2 * b2; acc[2][3] += a2 * b3;
            acc[3][0] += a3 * b0; acc[3][1] += a3 * b1; acc[3][2] += a3 * b2; acc[3][3] += a3 * b3;
        }
    }
    float* out = g_gram + ((size_t)(mat * Bz + b) * NCH + ch) * 4096;
    #pragma unroll
    for (int i = 0; i < 4; i++)
        #pragma unroll
        for (int q = 0; q < 4; q++)
            out[(t0 + i) * 64 + s0 + q] = acc[i][q];

    if (t0 == s0) {
        float* sv = g_sinv + mat * Mz + b * Lz + ch * 64;
        #pragma unroll
        for (int i = 0; i < 4; i++)
            sv[t0 + i] = 1.f / (acc[i][i] + 1e-6f);
    }
}

// ---------------- chunked delta-rule scan (in-warp q reduction) --------------
// thread map: w = tid>>5, lane; row r = w*8 + (lane&7); colgroup g = lane>>3.
#define SCAN_SMEM ((16384 + 4096 + 4096 + 4096 + 64) * 4)

__global__ __launch_bounds__(256, 2)
void scan_k()
{
    extern __shared__ float sm[];
    float* Ks = sm;              // [64][256]
    float* Q  = Ks + 16384;      // [64][64]
    float* As = Q  + 4096;       // [64][64]
    float* Us = As + 4096;       // [64][64]
    float* Bs = Us + 4096;       // [64]

    const int tid  = threadIdx.x;
    const int lane = tid & 31;
    const int w    = tid >> 5;
    const int rb   = blockIdx.x;
    const int mat  = blockIdx.y;
    const int b    = blockIdx.z;
    const int r    = w * 8 + (lane & 7);
    const int g    = lane >> 3;
    const int r0   = rb * 64;

    const float* kbase = (mat ? g_ke : g_ks) + (size_t)b * Lz * HALFz;
    const float* sv    = g_sinv + mat * Mz + b * Lz;
    const float* gbase = g_gram + (size_t)(mat * Bz + b) * NCH * 4096;

    ull M2[32];
    #pragma unroll
    for (int i = 0; i < 32; i++) M2[i] = 0ull;

    for (int ch = 0; ch < NCH; ch++) {
        const int c0   = ch * 64;
        const int clen = (ch == NCH - 1) ? 63 : 64;

        __syncthreads();
        #pragma unroll
        for (int q = 0; q < 16; q++) {
            int off = tid * 4 + q * 1024;
            *(float4*)(Ks + off) = *(const float4*)(kbase + (size_t)c0 * HALFz + off);
        }
        #pragma unroll
        for (int q = 0; q < 4; q++) {
            int off = tid * 4 + q * 1024;
            *(float4*)(As + off) = *(const float4*)(gbase + ch * 4096 + off);
        }
        if (tid < 64) Bs[tid] = sv[c0 + tid];
        __syncthreads();

        // ---- q phase: per-t partial dot + in-warp butterfly reduce
        #pragma unroll 1
        for (int t = 0; t < 64; t++) {
            ull a0 = 0ull, a1 = 0ull;
            const ulonglong2* kt4 = (const ulonglong2*)(Ks + t * 256 + g * 64);
            #pragma unroll
            for (int jj = 0; jj < 16; jj++) {
                ulonglong2 kv = kt4[jj];
                fma2(a0, M2[2 * jj],     kv.x);
                fma2(a1, M2[2 * jj + 1], kv.y);
            }
            float2 s0 = upk(a0), s1 = upk(a1);
            float p = (s0.x + s0.y) + (s1.x + s1.y);
            p += __shfl_xor_sync(0xffffffffu, p, 8);
            p += __shfl_xor_sync(0xffffffffu, p, 16);
            if (lane < 8) Q[t * 64 + r] = p;
        }
        __syncthreads();

        // ---- substitution: 4 sub-blocks of 16, right-looking updates
        for (int sb = 0; sb < 4; sb++) {
            if (tid < 64) {
                const int rr = tid;
                #pragma unroll 1
                for (int tt = 0; tt < 16; tt++) {
                    int t = sb * 16 + tt;
                    if (t < clen) {
                        float S = 0.f;
                        const float* At = As + t * 64;
                        for (int s = sb * 16; s < t; s++)
                            S += At[s] * Us[s * 64 + rr];
                        float alpha = (mat == 0) ? 1.f
                                     : (float)(c0 + t + 1) * (1.f / 1024.f);
                        float gam = alpha * Bs[t];
                        Us[t * 64 + rr] = alpha * Ks[t * 256 + r0 + rr]
                                        - gam * (Q[t * 64 + rr] + S);
                    }
                }
            }
            __syncthreads();
            if (sb < 3) {
                const int tstart = (sb + 1) * 16;
                const int nt = 64 - tstart;
                for (int o = tid; o < nt * 64; o += 256) {
                    int tt = tstart + (o >> 6);
                    int rr = o & 63;
                    float acc = 0.f;
                    const float* At = As + tt * 64;
                    #pragma unroll
                    for (int s = sb * 16; s < sb * 16 + 16; s++)
                        acc += At[s] * Us[s * 64 + rr];
                    Q[tt * 64 + rr] += acc;
                }
                __syncthreads();
            }
        }

        // ---- update: M += U^T K
        #pragma unroll 1
        for (int t = 0; t < clen; t++) {
            float u = Us[t * 64 + r];
            ull u2 = pk(u, u);
            const ulonglong2* kt4 = (const ulonglong2*)(Ks + t * 256 + g * 64);
            #pragma unroll
            for (int jj = 0; jj < 16; jj++) {
                ulonglong2 kv = kt4[jj];
                fma2(M2[2 * jj],     u2, kv.x);
                fma2(M2[2 * jj + 1], u2, kv.y);
            }
        }
    }

    // ---- final query: c = M . k_{L-1}
    {
        ull a0 = 0ull, a1 = 0ull;
        const ulonglong2* kt4 = (const ulonglong2*)(Ks + 63 * 256 + g * 64);
        #pragma unroll
        for (int jj = 0; jj < 16; jj++) {
            ulonglong2 kv = kt4[jj];
            fma2(a0, M2[2 * jj],     kv.x);
            fma2(a1, M2[2 * jj + 1], kv.y);
        }
        float2 s0 = upk(a0), s1 = upk(a1);
        float p = (s0.x + s0.y) + (s1.x + s1.y);
        p += __shfl_xor_sync(0xffffffffu, p, 8);
        p += __shfl_xor_sync(0xffffffffu, p, 16);
        if (lane < 8)
            g_c[b * (2 * HALFz) + mat * HALFz + r0 + r] = p;
    }
}

// ---------------- logits: single pass over W, all 64 rows --------------------
__global__ __launch_bounds__(256)
void out_k(const float* __restrict__ W, const float* __restrict__ ob,
           float* __restrict__ out)
{
    extern __shared__ float sc[];        // [512][64] k-major
    const int tid = threadIdx.x;

    for (int i = tid; i < 64 * 512; i += 256) {
        int m = i >> 9, k = i & 511;
        sc[k * 64 + m] = g_c[m * 512 + k];
    }
    __syncthreads();

    const int n = blockIdx.x * 256 + tid;
    ull acc2[32];
    #pragma unroll
    for (int q = 0; q < 32; q++) acc2[q] = 0ull;

    #pragma unroll 4
    for (int k = 0; k < 512; k++) {
        float wv = __ldg(W + (size_t)k * Vz + n);
        ull ww = pk(wv, wv);
        const ulonglong2* s2 = (const ulonglong2*)(sc + k * 64);
        #pragma unroll
        for (int q = 0; q < 16; q++) {
            ulonglong2 sv = s2[q];
            fma2(acc2[2 * q],     ww, sv.x);
            fma2(acc2[2 * q + 1], ww, sv.y);
        }
    }
    float bb = ob[n];
    #pragma unroll
    for (int q = 0; q < 32; q++) {
        float2 t = upk(acc2[q]);
        out[(size_t)(2 * q)     * Vz + n] = t.x + bb;
        out[(size_t)(2 * q + 1) * Vz + n] = t.y + bb;
    }
}

// ---------------- launch ------------------------------------------------------
extern "C" void kernel_launch(void* const* d_in, const int* in_sizes, int n_in,
                              void* d_out, int out_size)
{
    (void)in_sizes; (void)n_in; (void)out_size;
    const int*   seq    = (const int*)  d_in[0];
    const float* embed  = (const float*)d_in[1];
    const float* ff_w1  = (const float*)d_in[2];
    const float* ff_b1  = (const float*)d_in[3];
    const float* ff_w2  = (const float*)d_in[4];
    const float* ff_b2  = (const float*)d_in[5];
    const float* ln_g   = (const float*)d_in[6];
    const float* ln_b   = (const float*)d_in[7];
    const float* sem_w  = (const float*)d_in[8];
    const float* sem_b  = (const float*)d_in[9];
    const float* epi_w  = (const float*)d_in[10];
    const float* epi_b  = (const float*)d_in[11];
    const float* out_w  = (const float*)d_in[12];
    const float* out_b  = (const float*)d_in[13];
    float* out = (float*)d_out;

    cudaFuncSetAttribute(scan_k, cudaFuncAttributeMaxDynamicSharedMemorySize, SCAN_SMEM);
    cudaFuncSetAttribute(mgemm_k<0>, cudaFuncAttributeMaxDynamicSharedMemorySize, MG_SMEM);
    cudaFuncSetAttribute(mgemm_k<1>, cudaFuncAttributeMaxDynamicSharedMemorySize, MG_SMEM);
    cudaFuncSetAttribute(mgemm_k<2>, cudaFuncAttributeMaxDynamicSharedMemorySize, MG_SMEM);
    cudaFuncSetAttribute(out_k, cudaFuncAttributeMaxDynamicSharedMemorySize, 64 * 512 * 4);

    __nv_bfloat16 *w1hi, *w1lo, *w2hi, *w2lo, *swhi, *swlo, *ewhi, *ewlo;
    __nv_bfloat16 *embhi, *emblo, *r1hi, *r1lo, *hhi, *hlo;
    float *x_p, *ks_p, *ke_p;
    cudaGetSymbolAddress((void**)&w1hi, g_w1hi);
    cudaGetSymbolAddress((void**)&w1lo, g_w1lo);
    cudaGetSymbolAddress((void**)&w2hi, g_w2hi);
    cudaGetSymbolAddress((void**)&w2lo, g_w2lo);
    cudaGetSymbolAddress((void**)&swhi, g_swhi);
    cudaGetSymbolAddress((void**)&swlo, g_swlo);
    cudaGetSymbolAddress((void**)&ewhi, g_ewhi);
    cudaGetSymbolAddress((void**)&ewlo, g_ewlo);
    cudaGetSymbolAddress((void**)&embhi, g_embhi);
    cudaGetSymbolAddress((void**)&emblo, g_emblo);
    cudaGetSymbolAddress((void**)&r1hi, g_r1hi);
    cudaGetSymbolAddress((void**)&r1lo, g_r1lo);
    cudaGetSymbolAddress((void**)&hhi, g_hhi);
    cudaGetSymbolAddress((void**)&hlo, g_hlo);
    cudaGetSymbolAddress((void**)&x_p, g_x);
    cudaGetSymbolAddress((void**)&ks_p, g_ks);
    cudaGetSymbolAddress((void**)&ke_p, g_ke);

    // one-time splits
    const int emb4 = Vz * Hz / 4;
    esplit_k<<<(emb4 + 255) / 256, 256>>>(embed, embhi, emblo, emb4);
    wsplit_k<<<dim3(1024 / 32, 512 / 32), 256>>>(ff_w1, w1hi, w1lo, 512, 1024);
    wsplit_k<<<dim3(512 / 32, 1024 / 32), 256>>>(ff_w2, w2hi, w2lo, 1024, 512);
    wsplit_k<<<dim3(256 / 32, 512 / 32), 256>>>(sem_w, swhi, swlo, 512, 256);
    wsplit_k<<<dim3(256 / 32, 512 / 32), 256>>>(epi_w, ewhi, ewlo, 512, 256);

    // GEMMs
    mgemm_k<0><<<dim3(8, 512), 256, MG_SMEM>>>(seq, embed, embhi, emblo,
        w1hi, w1lo, ff_b1, nullptr, r1hi, r1lo, 512, 1024);
    mgemm_k<1><<<dim3(4, 512), 256, MG_SMEM>>>(seq, embed, r1hi, r1lo,
        w2hi, w2lo, ff_b2, x_p, nullptr, nullptr, 1024, 512);
    ln_k<<<Mz / 8, 256>>>(ln_g, ln_b);
    mgemm_k<2><<<dim3(2, 512), 256, MG_SMEM>>>(seq, embed, hhi, hlo,
        swhi, swlo, sem_b, ks_p, nullptr, nullptr, 512, 256);
    mgemm_k<2><<<dim3(2, 512), 256, MG_SMEM>>>(seq, embed, hhi, hlo,
        ewhi, ewlo, epi_b, ke_p, nullptr, nullptr, 512, 256);

    gram_k<<<dim3(NCH, 2, Bz), 256>>>();
    scan_k<<<dim3(4, 2, Bz), 256, SCAN_SMEM>>>();
    out_k<<<125, 256, 64 * 512 * 4>>>(out_w, out_b, out);
}

// round 14
// speedup vs baseline: 1.0101x; 1.0101x over previous
#include <cuda_runtime.h>
#include <cuda_bf16.h>
#include <cstdint>

#define Bz   64
#define Lz   1024
#define Hz   512
#define HALFz 256
#define Vz   32000
#define Mz   (Bz*Lz)          /* 65536 rows */
#define NCH  16               /* chunks of 64 steps */

typedef unsigned long long ull;

// ---------------- f32x2 packed-math helpers ----------------------------------
__device__ __forceinline__ void fma2(ull &d, ull a, ull b) {
    asm("fma.rn.f32x2 %0, %1, %2, %0;" : "+l"(d) : "l"(a), "l"(b));
}
__device__ __forceinline__ ull pk(float lo, float hi) {
    ull r; asm("mov.b64 %0, {%1, %2};" : "=l"(r) : "f"(lo), "f"(hi)); return r;
}
__device__ __forceinline__ float2 upk(ull v) {
    float2 r; asm("mov.b64 {%0, %1}, %2;" : "=f"(r.x), "=f"(r.y) : "l"(v)); return r;
}

// ---------------- warp-mma helpers -------------------------------------------
__device__ __forceinline__ uint32_t smem_u32(const void* p) {
    uint32_t a;
    asm("{ .reg .u64 t; cvta.to.shared.u64 t, %1; cvt.u32.u64 %0, t; }"
        : "=r"(a) : "l"(p));
    return a;
}
__device__ __forceinline__ void ldm4(uint32_t* r, uint32_t addr) {
    asm volatile("ldmatrix.sync.aligned.m8n8.x4.shared.b16 {%0,%1,%2,%3}, [%4];"
        : "=r"(r[0]), "=r"(r[1]), "=r"(r[2]), "=r"(r[3]) : "r"(addr));
}
__device__ __forceinline__ void mma_bf16(float* c, const uint32_t* a,
                                         const uint32_t* b) {
    asm volatile("mma.sync.aligned.m16n8k16.row.col.f32.bf16.bf16.f32 "
        "{%0,%1,%2,%3}, {%4,%5,%6,%7}, {%8,%9}, {%0,%1,%2,%3};"
        : "+f"(c[0]), "+f"(c[1]), "+f"(c[2]), "+f"(c[3])
        : "r"(a[0]), "r"(a[1]), "r"(a[2]), "r"(a[3]), "r"(b[0]), "r"(b[1]));
}
__device__ __forceinline__ void cpa16(uint32_t dst, const void* src) {
    asm volatile("cp.async.ca.shared.global [%0], [%1], 16;"
                 :: "r"(dst), "l"(src) : "memory");
}
__device__ __forceinline__ void cpa_wait_all() {
    asm volatile("cp.async.wait_all;" ::: "memory");
}

// ---------------- scratch ----------------------------------------------------
__device__ float g_relu[(size_t)Mz * 1024];
__device__ float g_x   [(size_t)Mz * Hz];
__device__ float g_h   [(size_t)Mz * Hz];
__device__ float g_ks  [(size_t)Mz * HALFz];
__device__ float g_ke  [(size_t)Mz * HALFz];
__device__ float g_sinv[2 * Mz];
__device__ float g_gram[(size_t)2 * Bz * NCH * 64 * 64];
__device__ float g_c   [Bz * 2 * HALFz];
__device__ __nv_bfloat16 g_w1hi[1024 * 512], g_w1lo[1024 * 512];
__device__ __nv_bfloat16 g_w2hi[512 * 1024], g_w2lo[512 * 1024];
__device__ __nv_bfloat16 g_swhi[256 * 512],  g_swlo[256 * 512];
__device__ __nv_bfloat16 g_ewhi[256 * 512],  g_ewlo[256 * 512];

// ---------------- weight transpose + bf16 split:  W[K][N] -> [N][K] hi/lo ----
__global__ __launch_bounds__(256)
void wsplit_k(const float* __restrict__ W, __nv_bfloat16* __restrict__ hi,
              __nv_bfloat16* __restrict__ lo, int K, int N)
{
    __shared__ float t[32][33];
    const int n0 = blockIdx.x * 32, k0 = blockIdx.y * 32;
    const int tx = threadIdx.x & 31, ty = threadIdx.x >> 5;
    #pragma unroll
    for (int p = 0; p < 4; p++) {
        int kk = ty + p * 8;
        t[kk][tx] = W[(size_t)(k0 + kk) * N + n0 + tx];
    }
    __syncthreads();
    #pragma unroll
    for (int p = 0; p < 4; p++) {
        int r = ty + p * 8;
        float v = t[tx][r];
        __nv_bfloat16 h = __float2bfloat16(v);
        __nv_bfloat16 l = __float2bfloat16(v - __bfloat162float(h));
        size_t o = (size_t)(n0 + r) * K + k0 + tx;
        hi[o] = h; lo[o] = l;
    }
}

// ---------------- HMMA split-bf16 GEMM (R10-proven form) ---------------------
// 128x128 block, BK=32, 8 warps (4m x 2n), warp tile 32x64, m16n8k16.
// MODE 0: A = embed[seq[m]] fp32 inline split, epi relu(d+bias) -> g_relu
// MODE 1: A = Afp,                             epi d+bias+embed gather -> g_x
// MODE 2: A = Afp,                             epi d+bias -> Cout
#define MG_STR  40
#define MG_AH   0
#define MG_AL   (128 * MG_STR)
#define MG_BH   (2 * 128 * MG_STR)
#define MG_BL   (3 * 128 * MG_STR)
#define MG_STAGE (4 * 128 * MG_STR)
#define MG_SMEM (2 * MG_STAGE * 2)

template<int MODE>
__global__ __launch_bounds__(256, 2)
void mgemm_k(const int* __restrict__ seq, const float* __restrict__ embed,
             const float* __restrict__ Afp,
             const __nv_bfloat16* __restrict__ Bhi,
             const __nv_bfloat16* __restrict__ Blo,
             const float* __restrict__ bias, float* __restrict__ Cout,
             int Kfull, int Nfull)
{
    extern __shared__ __nv_bfloat16 smb[];
    __shared__ int seqs[128];

    const int tid  = threadIdx.x;
    const int lane = tid & 31;
    const int wid  = tid >> 5;
    const int wm   = wid & 3;
    const int wn   = wid >> 2;
    const int m0 = blockIdx.y * 128;
    const int n0 = blockIdx.x * 128;

    if (MODE != 2 && tid < 128) seqs[tid] = seq[m0 + tid];
    __syncthreads();

    float acc[2][8][4];
    #pragma unroll
    for (int i = 0; i < 2; i++)
        #pragma unroll
        for (int n = 0; n < 8; n++)
            #pragma unroll
            for (int q = 0; q < 4; q++) acc[i][n][q] = 0.f;

    const int nk = Kfull >> 5;

    auto mg_load = [&](int kc, int s) {
        __nv_bfloat16* sb = smb + s * MG_STAGE;
        const int k0 = kc << 5;
        {   // B: pre-split bf16 [N][K] — async 16B copies
            const uint32_t sbu = smem_u32(sb);
            const int row0 = tid >> 2;
            const int k8   = (tid & 3) << 3;
            #pragma unroll
            for (int p = 0; p < 2; p++) {
                int n = row0 + p * 64;
                size_t o = (size_t)(n0 + n) * Kfull + k0 + k8;
                int d = n * MG_STR + k8;
                cpa16(sbu + (MG_BH + d) * 2, Bhi + o);
                cpa16(sbu + (MG_BL + d) * 2, Blo + o);
            }
        }
        {   // A: fp32 coalesced load -> hi/lo split -> STS
            const int row0 = tid >> 3;
            const int k4   = (tid & 7) << 2;
            #pragma unroll
            for (int p = 0; p < 4; p++) {
                int row = row0 + p * 32;
                const float* src;
                if (MODE == 0) src = embed + (size_t)seqs[row] * Hz + k0 + k4;
                else           src = Afp + (size_t)(m0 + row) * Kfull + k0 + k4;
                float4 v = *(const float4*)src;
                __nv_bfloat162 h01 = __floats2bfloat162_rn(v.x, v.y);
                __nv_bfloat162 h23 = __floats2bfloat162_rn(v.z, v.w);
                __nv_bfloat162 l01 = __floats2bfloat162_rn(
                    v.x - __bfloat162float(h01.x), v.y - __bfloat162float(h01.y));
                __nv_bfloat162 l23 = __floats2bfloat162_rn(
                    v.z - __bfloat162float(h23.x), v.w - __bfloat162float(h23.y));
                int o = row * MG_STR + k4;
                *(uint2*)(sb + MG_AH + o) = make_uint2(*(uint32_t*)&h01, *(uint32_t*)&h23);
                *(uint2*)(sb + MG_AL + o) = make_uint2(*(uint32_t*)&l01, *(uint32_t*)&l23);
            }
        }
    };

    mg_load(0, 0);
    cpa_wait_all();
    __syncthreads();

    for (int kc = 0; kc < nk; kc++) {
        if (kc + 1 < nk) mg_load(kc + 1, (kc + 1) & 1);

        const __nv_bfloat16* sb = smb + (kc & 1) * MG_STAGE;
        const uint32_t aH = smem_u32(sb + MG_AH);
        const uint32_t aL = smem_u32(sb + MG_AL);
        const uint32_t bH = smem_u32(sb + MG_BH);
        const uint32_t bL = smem_u32(sb + MG_BL);

        #pragma unroll
        for (int ks = 0; ks < 2; ks++) {
            uint32_t ah[2][4], al[2][4];
            const int ar = wm * 32 + (lane & 15);
            const int ac = ks * 16 + ((lane >> 4) << 3);
            #pragma unroll
            for (int i = 0; i < 2; i++) {
                uint32_t off = ((ar + i * 16) * MG_STR + ac) * 2;
                ldm4(ah[i], aH + off);
                ldm4(al[i], aL + off);
            }
            #pragma unroll
            for (int j = 0; j < 4; j++) {
                const int nr = wn * 64 + j * 16 + (lane & 7) + ((lane >> 4) << 3);
                const int kc2 = ks * 16 + (((lane >> 3) & 1) << 3);
                uint32_t off = (nr * MG_STR + kc2) * 2;
                uint32_t bh[4], bl[4];
                ldm4(bh, bH + off);
                ldm4(bl, bL + off);
                #pragma unroll
                for (int i = 0; i < 2; i++) {
                    mma_bf16(acc[i][2 * j],     ah[i], bh);
                    mma_bf16(acc[i][2 * j + 1], ah[i], bh + 2);
                    mma_bf16(acc[i][2 * j],     ah[i], bl);
                    mma_bf16(acc[i][2 * j + 1], ah[i], bl + 2);
                    mma_bf16(acc[i][2 * j],     al[i], bh);
                    mma_bf16(acc[i][2 * j + 1], al[i], bh + 2);
                }
            }
        }
        cpa_wait_all();
        __syncthreads();
    }

    // epilogue (float2 stores)
    #pragma unroll
    for (int i = 0; i < 2; i++) {
        int rlo = wm * 32 + i * 16 + (lane >> 2);
        #pragma unroll
        for (int n = 0; n < 8; n++) {
            int col = n0 + wn * 64 + n * 8 + (lane & 3) * 2;
            float b0 = bias[col], b1 = bias[col + 1];
            #pragma unroll
            for (int h = 0; h < 2; h++) {
                int rr = rlo + h * 8;
                size_t m = m0 + rr;
                float2 o;
                o.x = acc[i][n][2 * h + 0] + b0;
                o.y = acc[i][n][2 * h + 1] + b1;
                if (MODE == 0) { o.x = fmaxf(o.x, 0.f); o.y = fmaxf(o.y, 0.f); }
                if (MODE == 1) {
                    const float* e = embed + (size_t)seqs[rr] * Hz + col;
                    o.x += e[0]; o.y += e[1];
                }
                *(float2*)(Cout + m * Nfull + col) = o;
            }
        }
    }
}

// ---------------- LayerNorm: g_x -> g_h (fp32) -------------------------------
__global__ __launch_bounds__(256)
void ln_k(const float* __restrict__ gam, const float* __restrict__ bet)
{
    int row  = blockIdx.x * 8 + (threadIdx.x >> 5);
    int lane = threadIdx.x & 31;
    const float* x = g_x + (size_t)row * Hz;

    float4 v[4];
    float sum = 0.f, sq = 0.f;
    #pragma unroll
    for (int i = 0; i < 4; i++) {
        v[i] = *(const float4*)(x + lane * 4 + i * 128);
        sum += v[i].x + v[i].y + v[i].z + v[i].w;
        sq  += v[i].x * v[i].x + v[i].y * v[i].y + v[i].z * v[i].z + v[i].w * v[i].w;
    }
    #pragma unroll
    for (int off = 16; off > 0; off >>= 1) {
        sum += __shfl_xor_sync(0xffffffffu, sum, off);
        sq  += __shfl_xor_sync(0xffffffffu, sq,  off);
    }
    float mean = sum * (1.f / 512.f);
    float var  = sq  * (1.f / 512.f) - mean * mean;
    float rs   = rsqrtf(var + 1e-5f);

    float* o = g_h + (size_t)row * Hz;
    #pragma unroll
    for (int i = 0; i < 4; i++) {
        int col = lane * 4 + i * 128;
        float4 gg = *(const float4*)(gam + col);
        float4 bb = *(const float4*)(bet + col);
        float4 r;
        r.x = (v[i].x - mean) * rs * gg.x + bb.x;
        r.y = (v[i].y - mean) * rs * gg.y + bb.y;
        r.z = (v[i].z - mean) * rs * gg.z + bb.z;
        r.w = (v[i].w - mean) * rs * gg.w + bb.w;
        *(float4*)(o + col) = r;
    }
}

// ---------------- per-chunk Gram (fused 1/(k.k+eps) on the diagonal) ---------
__global__ __launch_bounds__(256)
void gram_k()
{
    __shared__ float Kh[64 * 129];
    const int ch = blockIdx.x, mat = blockIdx.y, b = blockIdx.z;
    const float* kbase = (mat ? g_ke : g_ks)
                         + (size_t)b * Lz * HALFz + (size_t)ch * 64 * HALFz;
    const int tid = threadIdx.x;
    const int t0 = (tid >> 4) * 4;
    const int s0 = (tid & 15) * 4;

    float acc[4][4];
    #pragma unroll
    for (int i = 0; i < 4; i++)
        #pragma unroll
        for (int q = 0; q < 4; q++) acc[i][q] = 0.f;

    const int row = tid >> 2;
    const int cb  = (tid & 3) * 32;

    for (int half = 0; half < 2; half++) {
        __syncthreads();
        #pragma unroll
        for (int d = 0; d < 8; d++) {
            float4 v = *(const float4*)(kbase + (size_t)row * HALFz + half * 128 + cb + 4 * d);
            float* w = Kh + row * 129 + cb + 4 * d;
            w[0] = v.x; w[1] = v.y; w[2] = v.z; w[3] = v.w;
        }
        __syncthreads();
        #pragma unroll 4
        for (int j = 0; j < 128; j++) {
            float a0 = Kh[(t0 + 0) * 129 + j], a1 = Kh[(t0 + 1) * 129 + j];
            float a2 = Kh[(t0 + 2) * 129 + j], a3 = Kh[(t0 + 3) * 129 + j];
            float b0 = Kh[(s0 + 0) * 129 + j], b1 = Kh[(s0 + 1) * 129 + j];
            float b2 = Kh[(s0 + 2) * 129 + j], b3 = Kh[(s0 + 3) * 129 + j];
            acc[0][0] += a0 * b0; acc[0][1] += a0 * b1; acc[0][2] += a0 * b2; acc[0][3] += a0 * b3;
            acc[1][0] += a1 * b0; acc[1][1] += a1 * b1; acc[1][2] += a1 * b2; acc[1][3] += a1 * b3;
            acc[2][0] += a2 * b0; acc[2][1] += a2 * b1; acc[2][2] += a2 * b2; acc[2][3] += a2 * b3;
            acc[3][0] += a3 * b0; acc[3][1] += a3 * b1; acc[3][2] += a3 * b2; acc[3][3] += a3 * b3;
        }
    }
    float* out = g_gram + ((size_t)(mat * Bz + b) * NCH + ch) * 4096;
    #pragma unroll
    for (int i = 0; i < 4; i++)
        #pragma unroll
        for (int q = 0; q < 4; q++)
            out[(t0 + i) * 64 + s0 + q] = acc[i][q];

    if (t0 == s0) {
        float* sv = g_sinv + mat * Mz + b * Lz + ch * 64;
        #pragma unroll
        for (int i = 0; i < 4; i++)
            sv[t0 + i] = 1.f / (acc[i][i] + 1e-6f);
    }
}

// ---------------- chunked delta-rule scan (in-warp q reduction) --------------
// thread map: w = tid>>5, lane; row r = w*8 + (lane&7); colgroup g = lane>>3.
#define SCAN_SMEM ((16384 + 4096 + 4096 + 4096 + 64) * 4)

__global__ __launch_bounds__(256, 2)
void scan_k()
{
    extern __shared__ float sm[];
    float* Ks = sm;              // [64][256]
    float* Q  = Ks + 16384;      // [64][64]
    float* As = Q  + 4096;       // [64][64]
    float* Us = As + 4096;       // [64][64]
    float* Bs = Us + 4096;       // [64]

    const int tid  = threadIdx.x;
    const int lane = tid & 31;
    const int w    = tid >> 5;
    const int rb   = blockIdx.x;
    const int mat  = blockIdx.y;
    const int b    = blockIdx.z;
    const int r    = w * 8 + (lane & 7);
    const int g    = lane >> 3;
    const int r0   = rb * 64;

    const float* kbase = (mat ? g_ke : g_ks) + (size_t)b * Lz * HALFz;
    const float* sv    = g_sinv + mat * Mz + b * Lz;
    const float* gbase = g_gram + (size_t)(mat * Bz + b) * NCH * 4096;

    ull M2[32];
    #pragma unroll
    for (int i = 0; i < 32; i++) M2[i] = 0ull;

    for (int ch = 0; ch < NCH; ch++) {
        const int c0   = ch * 64;
        const int clen = (ch == NCH - 1) ? 63 : 64;

        __syncthreads();
        #pragma unroll
        for (int q = 0; q < 16; q++) {
            int off = tid * 4 + q * 1024;
            *(float4*)(Ks + off) = *(const float4*)(kbase + (size_t)c0 * HALFz + off);
        }
        #pragma unroll
        for (int q = 0; q < 4; q++) {
            int off = tid * 4 + q * 1024;
            *(float4*)(As + off) = *(const float4*)(gbase + ch * 4096 + off);
        }
        if (tid < 64) Bs[tid] = sv[c0 + tid];
        __syncthreads();

        // ---- q phase: per-t partial dot + in-warp butterfly reduce
        #pragma unroll 1
        for (int t = 0; t < 64; t++) {
            ull a0 = 0ull, a1 = 0ull;
            const ulonglong2* kt4 = (const ulonglong2*)(Ks + t * 256 + g * 64);
            #pragma unroll
            for (int jj = 0; jj < 16; jj++) {
                ulonglong2 kv = kt4[jj];
                fma2(a0, M2[2 * jj],     kv.x);
                fma2(a1, M2[2 * jj + 1], kv.y);
            }
            float2 s0 = upk(a0), s1 = upk(a1);
            float p = (s0.x + s0.y) + (s1.x + s1.y);
            p += __shfl_xor_sync(0xffffffffu, p, 8);
            p += __shfl_xor_sync(0xffffffffu, p, 16);
            if (lane < 8) Q[t * 64 + r] = p;
        }
        __syncthreads();

        // ---- substitution: 4 sub-blocks of 16, right-looking updates
        for (int sb = 0; sb < 4; sb++) {
            if (tid < 64) {
                const int rr = tid;
                #pragma unroll 1
                for (int tt = 0; tt < 16; tt++) {
                    int t = sb * 16 + tt;
                    if (t < clen) {
                        float S = 0.f;
                        const float* At = As + t * 64;
                        for (int s = sb * 16; s < t; s++)
                            S += At[s] * Us[s * 64 + rr];
                        float alpha = (mat == 0) ? 1.f
                                     : (float)(c0 + t + 1) * (1.f / 1024.f);
                        float gam = alpha * Bs[t];
                        Us[t * 64 + rr] = alpha * Ks[t * 256 + r0 + rr]
                                        - gam * (Q[t * 64 + rr] + S);
                    }
                }
            }
            __syncthreads();
            if (sb < 3) {
                const int tstart = (sb + 1) * 16;
                const int nt = 64 - tstart;
                for (int o = tid; o < nt * 64; o += 256) {
                    int tt = tstart + (o >> 6);
                    int rr = o & 63;
                    float acc = 0.f;
                    const float* At = As + tt * 64;
                    #pragma unroll
                    for (int s = sb * 16; s < sb * 16 + 16; s++)
                        acc += At[s] * Us[s * 64 + rr];
                    Q[tt * 64 + rr] += acc;
                }
                __syncthreads();
            }
        }

        // ---- update: M += U^T K
        #pragma unroll 1
        for (int t = 0; t < clen; t++) {
            float u = Us[t * 64 + r];
            ull u2 = pk(u, u);
            const ulonglong2* kt4 = (const ulonglong2*)(Ks + t * 256 + g * 64);
            #pragma unroll
            for (int jj = 0; jj < 16; jj++) {
                ulonglong2 kv = kt4[jj];
                fma2(M2[2 * jj],     u2, kv.x);
                fma2(M2[2 * jj + 1], u2, kv.y);
            }
        }
    }

    // ---- final query: c = M . k_{L-1}
    {
        ull a0 = 0ull, a1 = 0ull;
        const ulonglong2* kt4 = (const ulonglong2*)(Ks + 63 * 256 + g * 64);
        #pragma unroll
        for (int jj = 0; jj < 16; jj++) {
            ulonglong2 kv = kt4[jj];
            fma2(a0, M2[2 * jj],     kv.x);
            fma2(a1, M2[2 * jj + 1], kv.y);
        }
        float2 s0 = upk(a0), s1 = upk(a1);
        float p = (s0.x + s0.y) + (s1.x + s1.y);
        p += __shfl_xor_sync(0xffffffffu, p, 8);
        p += __shfl_xor_sync(0xffffffffu, p, 16);
        if (lane < 8)
            g_c[b * (2 * HALFz) + mat * HALFz + r0 + r] = p;
    }
}

// ---------------- logits: single pass over W, all 64 rows --------------------
__global__ __launch_bounds__(256)
void out_k(const float* __restrict__ W, const float* __restrict__ ob,
           float* __restrict__ out)
{
    extern __shared__ float sc[];        // [512][64] k-major
    const int tid = threadIdx.x;

    for (int i = tid; i < 64 * 512; i += 256) {
        int m = i >> 9, k = i & 511;
        sc[k * 64 + m] = g_c[m * 512 + k];
    }
    __syncthreads();

    const int n = blockIdx.x * 256 + tid;
    ull acc2[32];
    #pragma unroll
    for (int q = 0; q < 32; q++) acc2[q] = 0ull;

    #pragma unroll 4
    for (int k = 0; k < 512; k++) {
        float wv = __ldg(W + (size_t)k * Vz + n);
        ull ww = pk(wv, wv);
        const ulonglong2* s2 = (const ulonglong2*)(sc + k * 64);
        #pragma unroll
        for (int q = 0; q < 16; q++) {
            ulonglong2 sv = s2[q];
            fma2(acc2[2 * q],     ww, sv.x);
            fma2(acc2[2 * q + 1], ww, sv.y);
        }
    }
    float bb = ob[n];
    #pragma unroll
    for (int q = 0; q < 32; q++) {
        float2 t = upk(acc2[q]);
        out[(size_t)(2 * q)     * Vz + n] = t.x + bb;
        out[(size_t)(2 * q + 1) * Vz + n] = t.y + bb;
    }
}

// ---------------- launch ------------------------------------------------------
extern "C" void kernel_launch(void* const* d_in, const int* in_sizes, int n_in,
                              void* d_out, int out_size)
{
    (void)in_sizes; (void)n_in; (void)out_size;
    const int*   seq    = (const int*)  d_in[0];
    const float* embed  = (const float*)d_in[1];
    const float* ff_w1  = (const float*)d_in[2];
    const float* ff_b1  = (const float*)d_in[3];
    const float* ff_w2  = (const float*)d_in[4];
    const float* ff_b2  = (const float*)d_in[5];
    const float* ln_g   = (const float*)d_in[6];
    const float* ln_b   = (const float*)d_in[7];
    const float* sem_w  = (const float*)d_in[8];
    const float* sem_b  = (const float*)d_in[9];
    const float* epi_w  = (const float*)d_in[10];
    const float* epi_b  = (const float*)d_in[11];
    const float* out_w  = (const float*)d_in[12];
    const float* out_b  = (const float*)d_in[13];
    float* out = (float*)d_out;

    cudaFuncSetAttribute(scan_k, cudaFuncAttributeMaxDynamicSharedMemorySize, SCAN_SMEM);
    cudaFuncSetAttribute(mgemm_k<0>, cudaFuncAttributeMaxDynamicSharedMemorySize, MG_SMEM);
    cudaFuncSetAttribute(mgemm_k<1>, cudaFuncAttributeMaxDynamicSharedMemorySize, MG_SMEM);
    cudaFuncSetAttribute(mgemm_k<2>, cudaFuncAttributeMaxDynamicSharedMemorySize, MG_SMEM);
    cudaFuncSetAttribute(out_k, cudaFuncAttributeMaxDynamicSharedMemorySize, 64 * 512 * 4);

    __nv_bfloat16 *w1hi, *w1lo, *w2hi, *w2lo, *swhi, *swlo, *ewhi, *ewlo;
    float *relu_p, *x_p, *h_p, *ks_p, *ke_p;
    cudaGetSymbolAddress((void**)&w1hi, g_w1hi);
    cudaGetSymbolAddress((void**)&w1lo, g_w1lo);
    cudaGetSymbolAddress((void**)&w2hi, g_w2hi);
    cudaGetSymbolAddress((void**)&w2lo, g_w2lo);
    cudaGetSymbolAddress((void**)&swhi, g_swhi);
    cudaGetSymbolAddress((void**)&swlo, g_swlo);
    cudaGetSymbolAddress((void**)&ewhi, g_ewhi);
    cudaGetSymbolAddress((void**)&ewlo, g_ewlo);
    cudaGetSymbolAddress((void**)&relu_p, g_relu);
    cudaGetSymbolAddress((void**)&x_p, g_x);
    cudaGetSymbolAddress((void**)&h_p, g_h);
    cudaGetSymbolAddress((void**)&ks_p, g_ks);
    cudaGetSymbolAddress((void**)&ke_p, g_ke);

    wsplit_k<<<dim3(1024 / 32, 512 / 32), 256>>>(ff_w1, w1hi, w1lo, 512, 1024);
    wsplit_k<<<dim3(512 / 32, 1024 / 32), 256>>>(ff_w2, w2hi, w2lo, 1024, 512);
    wsplit_k<<<dim3(256 / 32, 512 / 32), 256>>>(sem_w, swhi, swlo, 512, 256);
    wsplit_k<<<dim3(256 / 32, 512 / 32), 256>>>(epi_w, ewhi, ewlo, 512, 256);

    mgemm_k<0><<<dim3(8, 512), 256, MG_SMEM>>>(seq, embed, nullptr, w1hi, w1lo,
                                               ff_b1, relu_p, 512, 1024);
    mgemm_k<1><<<dim3(4, 512), 256, MG_SMEM>>>(seq, embed, relu_p, w2hi, w2lo,
                                               ff_b2, x_p, 1024, 512);
    ln_k<<<Mz / 8, 256>>>(ln_g, ln_b);
    mgemm_k<2><<<dim3(2, 512), 256, MG_SMEM>>>(seq, embed, h_p, swhi, swlo,
                                               sem_b, ks_p, 512, 256);
    mgemm_k<2><<<dim3(2, 512), 256, MG_SMEM>>>(seq, embed, h_p, ewhi, ewlo,
                                               epi_b, ke_p, 512, 256);
    gram_k<<<dim3(NCH, 2, Bz), 256>>>();
    scan_k<<<dim3(4, 2, Bz), 256, SCAN_SMEM>>>();
    out_k<<<125, 256, 64 * 512 * 4>>>(out_w, out_b, out);
}

// round 15
// speedup vs baseline: 1.2732x; 1.2605x over previous
#include <cuda_runtime.h>
#include <cuda_bf16.h>
#include <cstdint>

#define Bz   64
#define Lz   1024
#define Hz   512
#define HALFz 256
#define Vz   32000
#define Mz   (Bz*Lz)          /* 65536 rows */
#define NCH  16               /* chunks of 64 steps */

typedef unsigned long long ull;

// ---------------- f32x2 packed-math helpers ----------------------------------
__device__ __forceinline__ void fma2(ull &d, ull a, ull b) {
    asm("fma.rn.f32x2 %0, %1, %2, %0;" : "+l"(d) : "l"(a), "l"(b));
}
__device__ __forceinline__ ull pk(float lo, float hi) {
    ull r; asm("mov.b64 %0, {%1, %2};" : "=l"(r) : "f"(lo), "f"(hi)); return r;
}
__device__ __forceinline__ float2 upk(ull v) {
    float2 r; asm("mov.b64 {%0, %1}, %2;" : "=f"(r.x), "=f"(r.y) : "l"(v)); return r;
}

// ---------------- warp-mma helpers -------------------------------------------
__device__ __forceinline__ uint32_t smem_u32(const void* p) {
    uint32_t a;
    asm("{ .reg .u64 t; cvta.to.shared.u64 t, %1; cvt.u32.u64 %0, t; }"
        : "=r"(a) : "l"(p));
    return a;
}
__device__ __forceinline__ void ldm4(uint32_t* r, uint32_t addr) {
    asm volatile("ldmatrix.sync.aligned.m8n8.x4.shared.b16 {%0,%1,%2,%3}, [%4];"
        : "=r"(r[0]), "=r"(r[1]), "=r"(r[2]), "=r"(r[3]) : "r"(addr));
}
__device__ __forceinline__ void mma_bf16(float* c, const uint32_t* a,
                                         const uint32_t* b) {
    asm volatile("mma.sync.aligned.m16n8k16.row.col.f32.bf16.bf16.f32 "
        "{%0,%1,%2,%3}, {%4,%5,%6,%7}, {%8,%9}, {%0,%1,%2,%3};"
        : "+f"(c[0]), "+f"(c[1]), "+f"(c[2]), "+f"(c[3])
        : "r"(a[0]), "r"(a[1]), "r"(a[2]), "r"(a[3]), "r"(b[0]), "r"(b[1]));
}
__device__ __forceinline__ void cpa16(uint32_t dst, const void* src) {
    asm volatile("cp.async.ca.shared.global [%0], [%1], 16;"
                 :: "r"(dst), "l"(src) : "memory");
}
__device__ __forceinline__ void cpa_wait_all() {
    asm volatile("cp.async.wait_all;" ::: "memory");
}

// ---------------- scratch ----------------------------------------------------
__device__ float g_relu[(size_t)Mz * 1024];
__device__ float g_x   [(size_t)Mz * Hz];
__device__ float g_h   [(size_t)Mz * Hz];
__device__ float g_ks  [(size_t)Mz * HALFz];
__device__ float g_ke  [(size_t)Mz * HALFz];
__device__ float g_sinv[2 * Mz];
__device__ float g_gram[(size_t)2 * Bz * NCH * 64 * 64];
__device__ float g_c   [Bz * 2 * HALFz];
__device__ __nv_bfloat16 g_w1hi[1024 * 512], g_w1lo[1024 * 512];
__device__ __nv_bfloat16 g_w2hi[512 * 1024], g_w2lo[512 * 1024];
__device__ __nv_bfloat16 g_swhi[256 * 512],  g_swlo[256 * 512];
__device__ __nv_bfloat16 g_ewhi[256 * 512],  g_ewlo[256 * 512];

// ---------------- weight transpose + bf16 split:  W[K][N] -> [N][K] hi/lo ----
__global__ __launch_bounds__(256)
void wsplit_k(const float* __restrict__ W, __nv_bfloat16* __restrict__ hi,
              __nv_bfloat16* __restrict__ lo, int K, int N)
{
    __shared__ float t[32][33];
    const int n0 = blockIdx.x * 32, k0 = blockIdx.y * 32;
    const int tx = threadIdx.x & 31, ty = threadIdx.x >> 5;
    #pragma unroll
    for (int p = 0; p < 4; p++) {
        int kk = ty + p * 8;
        t[kk][tx] = W[(size_t)(k0 + kk) * N + n0 + tx];
    }
    __syncthreads();
    #pragma unroll
    for (int p = 0; p < 4; p++) {
        int r = ty + p * 8;
        float v = t[tx][r];
        __nv_bfloat16 h = __float2bfloat16(v);
        __nv_bfloat16 l = __float2bfloat16(v - __bfloat162float(h));
        size_t o = (size_t)(n0 + r) * K + k0 + tx;
        hi[o] = h; lo[o] = l;
    }
}

// ---------------- HMMA split-bf16 GEMM (R10-proven form) ---------------------
#define MG_STR  40
#define MG_AH   0
#define MG_AL   (128 * MG_STR)
#define MG_BH   (2 * 128 * MG_STR)
#define MG_BL   (3 * 128 * MG_STR)
#define MG_STAGE (4 * 128 * MG_STR)
#define MG_SMEM (2 * MG_STAGE * 2)

template<int MODE>
__global__ __launch_bounds__(256, 2)
void mgemm_k(const int* __restrict__ seq, const float* __restrict__ embed,
             const float* __restrict__ Afp,
             const __nv_bfloat16* __restrict__ Bhi,
             const __nv_bfloat16* __restrict__ Blo,
             const float* __restrict__ bias, float* __restrict__ Cout,
             int Kfull, int Nfull)
{
    extern __shared__ __nv_bfloat16 smb[];
    __shared__ int seqs[128];

    const int tid  = threadIdx.x;
    const int lane = tid & 31;
    const int wid  = tid >> 5;
    const int wm   = wid & 3;
    const int wn   = wid >> 2;
    const int m0 = blockIdx.y * 128;
    const int n0 = blockIdx.x * 128;

    if (MODE != 2 && tid < 128) seqs[tid] = seq[m0 + tid];
    __syncthreads();

    float acc[2][8][4];
    #pragma unroll
    for (int i = 0; i < 2; i++)
        #pragma unroll
        for (int n = 0; n < 8; n++)
            #pragma unroll
            for (int q = 0; q < 4; q++) acc[i][n][q] = 0.f;

    const int nk = Kfull >> 5;

    auto mg_load = [&](int kc, int s) {
        __nv_bfloat16* sb = smb + s * MG_STAGE;
        const int k0 = kc << 5;
        {   // B: pre-split bf16 [N][K] — async 16B copies
            const uint32_t sbu = smem_u32(sb);
            const int row0 = tid >> 2;
            const int k8   = (tid & 3) << 3;
            #pragma unroll
            for (int p = 0; p < 2; p++) {
                int n = row0 + p * 64;
                size_t o = (size_t)(n0 + n) * Kfull + k0 + k8;
                int d = n * MG_STR + k8;
                cpa16(sbu + (MG_BH + d) * 2, Bhi + o);
                cpa16(sbu + (MG_BL + d) * 2, Blo + o);
            }
        }
        {   // A: fp32 coalesced load -> hi/lo split -> STS
            const int row0 = tid >> 3;
            const int k4   = (tid & 7) << 2;
            #pragma unroll
            for (int p = 0; p < 4; p++) {
                int row = row0 + p * 32;
                const float* src;
                if (MODE == 0) src = embed + (size_t)seqs[row] * Hz + k0 + k4;
                else           src = Afp + (size_t)(m0 + row) * Kfull + k0 + k4;
                float4 v = *(const float4*)src;
                __nv_bfloat162 h01 = __floats2bfloat162_rn(v.x, v.y);
                __nv_bfloat162 h23 = __floats2bfloat162_rn(v.z, v.w);
                __nv_bfloat162 l01 = __floats2bfloat162_rn(
                    v.x - __bfloat162float(h01.x), v.y - __bfloat162float(h01.y));
                __nv_bfloat162 l23 = __floats2bfloat162_rn(
                    v.z - __bfloat162float(h23.x), v.w - __bfloat162float(h23.y));
                int o = row * MG_STR + k4;
                *(uint2*)(sb + MG_AH + o) = make_uint2(*(uint32_t*)&h01, *(uint32_t*)&h23);
                *(uint2*)(sb + MG_AL + o) = make_uint2(*(uint32_t*)&l01, *(uint32_t*)&l23);
            }
        }
    };

    mg_load(0, 0);
    cpa_wait_all();
    __syncthreads();

    for (int kc = 0; kc < nk; kc++) {
        if (kc + 1 < nk) mg_load(kc + 1, (kc + 1) & 1);

        const __nv_bfloat16* sb = smb + (kc & 1) * MG_STAGE;
        const uint32_t aH = smem_u32(sb + MG_AH);
        const uint32_t aL = smem_u32(sb + MG_AL);
        const uint32_t bH = smem_u32(sb + MG_BH);
        const uint32_t bL = smem_u32(sb + MG_BL);

        #pragma unroll
        for (int ks = 0; ks < 2; ks++) {
            uint32_t ah[2][4], al[2][4];
            const int ar = wm * 32 + (lane & 15);
            const int ac = ks * 16 + ((lane >> 4) << 3);
            #pragma unroll
            for (int i = 0; i < 2; i++) {
                uint32_t off = ((ar + i * 16) * MG_STR + ac) * 2;
                ldm4(ah[i], aH + off);
                ldm4(al[i], aL + off);
            }
            #pragma unroll
            for (int j = 0; j < 4; j++) {
                const int nr = wn * 64 + j * 16 + (lane & 7) + ((lane >> 4) << 3);
                const int kc2 = ks * 16 + (((lane >> 3) & 1) << 3);
                uint32_t off = (nr * MG_STR + kc2) * 2;
                uint32_t bh[4], bl[4];
                ldm4(bh, bH + off);
                ldm4(bl, bL + off);
                #pragma unroll
                for (int i = 0; i < 2; i++) {
                    mma_bf16(acc[i][2 * j],     ah[i], bh);
                    mma_bf16(acc[i][2 * j + 1], ah[i], bh + 2);
                    mma_bf16(acc[i][2 * j],     ah[i], bl);
                    mma_bf16(acc[i][2 * j + 1], ah[i], bl + 2);
                    mma_bf16(acc[i][2 * j],     al[i], bh);
                    mma_bf16(acc[i][2 * j + 1], al[i], bh + 2);
                }
            }
        }
        cpa_wait_all();
        __syncthreads();
    }

    // epilogue (float2 stores)
    #pragma unroll
    for (int i = 0; i < 2; i++) {
        int rlo = wm * 32 + i * 16 + (lane >> 2);
        #pragma unroll
        for (int n = 0; n < 8; n++) {
            int col = n0 + wn * 64 + n * 8 + (lane & 3) * 2;
            float b0 = bias[col], b1 = bias[col + 1];
            #pragma unroll
            for (int h = 0; h < 2; h++) {
                int rr = rlo + h * 8;
                size_t m = m0 + rr;
                float2 o;
                o.x = acc[i][n][2 * h + 0] + b0;
                o.y = acc[i][n][2 * h + 1] + b1;
                if (MODE == 0) { o.x = fmaxf(o.x, 0.f); o.y = fmaxf(o.y, 0.f); }
                if (MODE == 1) {
                    const float* e = embed + (size_t)seqs[rr] * Hz + col;
                    o.x += e[0]; o.y += e[1];
                }
                *(float2*)(Cout + m * Nfull + col) = o;
            }
        }
    }
}

// ---------------- LayerNorm: g_x -> g_h (fp32) -------------------------------
__global__ __launch_bounds__(256)
void ln_k(const float* __restrict__ gam, const float* __restrict__ bet)
{
    int row  = blockIdx.x * 8 + (threadIdx.x >> 5);
    int lane = threadIdx.x & 31;
    const float* x = g_x + (size_t)row * Hz;

    float4 v[4];
    float sum = 0.f, sq = 0.f;
    #pragma unroll
    for (int i = 0; i < 4; i++) {
        v[i] = *(const float4*)(x + lane * 4 + i * 128);
        sum += v[i].x + v[i].y + v[i].z + v[i].w;
        sq  += v[i].x * v[i].x + v[i].y * v[i].y + v[i].z * v[i].z + v[i].w * v[i].w;
    }
    #pragma unroll
    for (int off = 16; off > 0; off >>= 1) {
        sum += __shfl_xor_sync(0xffffffffu, sum, off);
        sq  += __shfl_xor_sync(0xffffffffu, sq,  off);
    }
    float mean = sum * (1.f / 512.f);
    float var  = sq  * (1.f / 512.f) - mean * mean;
    float rs   = rsqrtf(var + 1e-5f);

    float* o = g_h + (size_t)row * Hz;
    #pragma unroll
    for (int i = 0; i < 4; i++) {
        int col = lane * 4 + i * 128;
        float4 gg = *(const float4*)(gam + col);
        float4 bb = *(const float4*)(bet + col);
        float4 r;
        r.x = (v[i].x - mean) * rs * gg.x + bb.x;
        r.y = (v[i].y - mean) * rs * gg.y + bb.y;
        r.z = (v[i].z - mean) * rs * gg.z + bb.z;
        r.w = (v[i].w - mean) * rs * gg.w + bb.w;
        *(float4*)(o + col) = r;
    }
}

// ---------------- per-chunk Gram (fused 1/(k.k+eps) on the diagonal) ---------
__global__ __launch_bounds__(256)
void gram_k()
{
    __shared__ float Kh[64 * 129];
    const int ch = blockIdx.x, mat = blockIdx.y, b = blockIdx.z;
    const float* kbase = (mat ? g_ke : g_ks)
                         + (size_t)b * Lz * HALFz + (size_t)ch * 64 * HALFz;
    const int tid = threadIdx.x;
    const int t0 = (tid >> 4) * 4;
    const int s0 = (tid & 15) * 4;

    float acc[4][4];
    #pragma unroll
    for (int i = 0; i < 4; i++)
        #pragma unroll
        for (int q = 0; q < 4; q++) acc[i][q] = 0.f;

    const int row = tid >> 2;
    const int cb  = (tid & 3) * 32;

    for (int half = 0; half < 2; half++) {
        __syncthreads();
        #pragma unroll
        for (int d = 0; d < 8; d++) {
            float4 v = *(const float4*)(kbase + (size_t)row * HALFz + half * 128 + cb + 4 * d);
            float* w = Kh + row * 129 + cb + 4 * d;
            w[0] = v.x; w[1] = v.y; w[2] = v.z; w[3] = v.w;
        }
        __syncthreads();
        #pragma unroll 4
        for (int j = 0; j < 128; j++) {
            float a0 = Kh[(t0 + 0) * 129 + j], a1 = Kh[(t0 + 1) * 129 + j];
            float a2 = Kh[(t0 + 2) * 129 + j], a3 = Kh[(t0 + 3) * 129 + j];
            float b0 = Kh[(s0 + 0) * 129 + j], b1 = Kh[(s0 + 1) * 129 + j];
            float b2 = Kh[(s0 + 2) * 129 + j], b3 = Kh[(s0 + 3) * 129 + j];
            acc[0][0] += a0 * b0; acc[0][1] += a0 * b1; acc[0][2] += a0 * b2; acc[0][3] += a0 * b3;
            acc[1][0] += a1 * b0; acc[1][1] += a1 * b1; acc[1][2] += a1 * b2; acc[1][3] += a1 * b3;
            acc[2][0] += a2 * b0; acc[2][1] += a2 * b1; acc[2][2] += a2 * b2; acc[2][3] += a2 * b3;
            acc[3][0] += a3 * b0; acc[3][1] += a3 * b1; acc[3][2] += a3 * b2; acc[3][3] += a3 * b3;
        }
    }
    float* out = g_gram + ((size_t)(mat * Bz + b) * NCH + ch) * 4096;
    #pragma unroll
    for (int i = 0; i < 4; i++)
        #pragma unroll
        for (int q = 0; q < 4; q++)
            out[(t0 + i) * 64 + s0 + q] = acc[i][q];

    if (t0 == s0) {
        float* sv = g_sinv + mat * Mz + b * Lz + ch * 64;
        #pragma unroll
        for (int i = 0; i < 4; i++)
            sv[t0 + i] = 1.f / (acc[i][i] + 1e-6f);
    }
}

// ---------------- chunked delta-rule scan ------------------------------------
// In-warp q reduction with CONFLICT-FREE padded-group Ks layout:
//   Ks stored as [group][t][64], group stride 4104 floats (4104 mod 32 = 8,
//   so the 4 groups' LDS.128 addresses land in disjoint bank quads).
// thread map: w = tid>>5, lane; row r = w*8 + (lane&7); colgroup g = lane>>3.
#define KSP_G 4104
#define SCAN_SMEM ((4 * KSP_G + 4096 + 4096 + 4096 + 64) * 4)

__global__ __launch_bounds__(256, 2)
void scan_k()
{
    extern __shared__ float sm[];
    float* Ks = sm;                  // [4][64][64] padded, stride KSP_G
    float* Q  = Ks + 4 * KSP_G;      // [64][64]
    float* As = Q  + 4096;           // [64][64]
    float* Us = As + 4096;           // [64][64]
    float* Bs = Us + 4096;           // [64]

    const int tid  = threadIdx.x;
    const int lane = tid & 31;
    const int w    = tid >> 5;
    const int rb   = blockIdx.x;
    const int mat  = blockIdx.y;
    const int b    = blockIdx.z;
    const int r    = w * 8 + (lane & 7);
    const int g    = lane >> 3;
    const int r0   = rb * 64;

    const float* kbase = (mat ? g_ke : g_ks) + (size_t)b * Lz * HALFz;
    const float* sv    = g_sinv + mat * Mz + b * Lz;
    const float* gbase = g_gram + (size_t)(mat * Bz + b) * NCH * 4096;

    float* Kg = Ks + g * KSP_G;          // this lane's column-group base

    ull M2[32];
    #pragma unroll
    for (int i = 0; i < 32; i++) M2[i] = 0ull;

    for (int ch = 0; ch < NCH; ch++) {
        const int c0   = ch * 64;
        const int clen = (ch == NCH - 1) ? 63 : 64;

        __syncthreads();
        // load K chunk into padded [group][t][64] layout
        #pragma unroll
        for (int q = 0; q < 16; q++) {
            int off = tid * 4 + q * 1024;
            int t = off >> 8, c = off & 255;
            float4 v = *(const float4*)(kbase + (size_t)c0 * HALFz + off);
            *(float4*)(Ks + (c >> 6) * KSP_G + t * 64 + (c & 63)) = v;
        }
        #pragma unroll
        for (int q = 0; q < 4; q++) {
            int off = tid * 4 + q * 1024;
            *(float4*)(As + off) = *(const float4*)(gbase + ch * 4096 + off);
        }
        if (tid < 64) Bs[tid] = sv[c0 + tid];
        __syncthreads();

        // ---- q phase: partial dot per group + in-warp butterfly reduce
        #pragma unroll 1
        for (int t = 0; t < 64; t++) {
            ull a0 = 0ull, a1 = 0ull;
            const ulonglong2* kt4 = (const ulonglong2*)(Kg + t * 64);
            #pragma unroll
            for (int jj = 0; jj < 16; jj++) {
                ulonglong2 kv = kt4[jj];
                fma2(a0, M2[2 * jj],     kv.x);
                fma2(a1, M2[2 * jj + 1], kv.y);
            }
            float2 s0 = upk(a0), s1 = upk(a1);
            float p = (s0.x + s0.y) + (s1.x + s1.y);
            p += __shfl_xor_sync(0xffffffffu, p, 8);
            p += __shfl_xor_sync(0xffffffffu, p, 16);
            if (lane < 8) Q[t * 64 + r] = p;
        }
        __syncthreads();

        // ---- substitution: 4 sub-blocks of 16, right-looking updates
        for (int sb = 0; sb < 4; sb++) {
            if (tid < 64) {
                const int rr = tid;
                #pragma unroll 1
                for (int tt = 0; tt < 16; tt++) {
                    int t = sb * 16 + tt;
                    if (t < clen) {
                        float S = 0.f;
                        const float* At = As + t * 64;
                        for (int s = sb * 16; s < t; s++)
                            S += At[s] * Us[s * 64 + rr];
                        float alpha = (mat == 0) ? 1.f
                                     : (float)(c0 + t + 1) * (1.f / 1024.f);
                        float gam = alpha * Bs[t];
                        Us[t * 64 + rr] = alpha * Ks[rb * KSP_G + t * 64 + rr]
                                        - gam * (Q[t * 64 + rr] + S);
                    }
                }
            }
            __syncthreads();
            if (sb < 3) {
                const int tstart = (sb + 1) * 16;
                const int nt = 64 - tstart;
                for (int o = tid; o < nt * 64; o += 256) {
                    int tt = tstart + (o >> 6);
                    int rr = o & 63;
                    float acc = 0.f;
                    const float* At = As + tt * 64;
                    #pragma unroll
                    for (int s = sb * 16; s < sb * 16 + 16; s++)
                        acc += At[s] * Us[s * 64 + rr];
                    Q[tt * 64 + rr] += acc;
                }
                __syncthreads();
            }
        }

        // ---- update: M += U^T K
        #pragma unroll 1
        for (int t = 0; t < clen; t++) {
            float u = Us[t * 64 + r];
            ull u2 = pk(u, u);
            const ulonglong2* kt4 = (const ulonglong2*)(Kg + t * 64);
            #pragma unroll
            for (int jj = 0; jj < 16; jj++) {
                ulonglong2 kv = kt4[jj];
                fma2(M2[2 * jj],     u2, kv.x);
                fma2(M2[2 * jj + 1], u2, kv.y);
            }
        }
    }

    // ---- final query: c = M . k_{L-1}
    {
        ull a0 = 0ull, a1 = 0ull;
        const ulonglong2* kt4 = (const ulonglong2*)(Kg + 63 * 64);
        #pragma unroll
        for (int jj = 0; jj < 16; jj++) {
            ulonglong2 kv = kt4[jj];
            fma2(a0, M2[2 * jj],     kv.x);
            fma2(a1, M2[2 * jj + 1], kv.y);
        }
        float2 s0 = upk(a0), s1 = upk(a1);
        float p = (s0.x + s0.y) + (s1.x + s1.y);
        p += __shfl_xor_sync(0xffffffffu, p, 8);
        p += __shfl_xor_sync(0xffffffffu, p, 16);
        if (lane < 8)
            g_c[b * (2 * HALFz) + mat * HALFz + r0 + r] = p;
    }
}

// ---------------- logits: single pass over W, all 64 rows --------------------
__global__ __launch_bounds__(256)
void out_k(const float* __restrict__ W, const float* __restrict__ ob,
           float* __restrict__ out)
{
    extern __shared__ float sc[];        // [512][64] k-major
    const int tid = threadIdx.x;

    for (int i = tid; i < 64 * 512; i += 256) {
        int m = i >> 9, k = i & 511;
        sc[k * 64 + m] = g_c[m * 512 + k];
    }
    __syncthreads();

    const int n = blockIdx.x * 256 + tid;
    ull acc2[32];
    #pragma unroll
    for (int q = 0; q < 32; q++) acc2[q] = 0ull;

    #pragma unroll 4
    for (int k = 0; k < 512; k++) {
        float wv = __ldg(W + (size_t)k * Vz + n);
        ull ww = pk(wv, wv);
        const ulonglong2* s2 = (const ulonglong2*)(sc + k * 64);
        #pragma unroll
        for (int q = 0; q < 16; q++) {
            ulonglong2 sv = s2[q];
            fma2(acc2[2 * q],     ww, sv.x);
            fma2(acc2[2 * q + 1], ww, sv.y);
        }
    }
    float bb = ob[n];
    #pragma unroll
    for (int q = 0; q < 32; q++) {
        float2 t = upk(acc2[q]);
        out[(size_t)(2 * q)     * Vz + n] = t.x + bb;
        out[(size_t)(2 * q + 1) * Vz + n] = t.y + bb;
    }
}

// ---------------- launch ------------------------------------------------------
extern "C" void kernel_launch(void* const* d_in, const int* in_sizes, int n_in,
                              void* d_out, int out_size)
{
    (void)in_sizes; (void)n_in; (void)out_size;
    const int*   seq    = (const int*)  d_in[0];
    const float* embed  = (const float*)d_in[1];
    const float* ff_w1  = (const float*)d_in[2];
    const float* ff_b1  = (const float*)d_in[3];
    const float* ff_w2  = (const float*)d_in[4];
    const float* ff_b2  = (const float*)d_in[5];
    const float* ln_g   = (const float*)d_in[6];
    const float* ln_b   = (const float*)d_in[7];
    const float* sem_w  = (const float*)d_in[8];
    const float* sem_b  = (const float*)d_in[9];
    const float* epi_w  = (const float*)d_in[10];
    const float* epi_b  = (const float*)d_in[11];
    const float* out_w  = (const float*)d_in[12];
    const float* out_b  = (const float*)d_in[13];
    float* out = (float*)d_out;

    cudaFuncSetAttribute(scan_k, cudaFuncAttributeMaxDynamicSharedMemorySize, SCAN_SMEM);
    cudaFuncSetAttribute(mgemm_k<0>, cudaFuncAttributeMaxDynamicSharedMemorySize, MG_SMEM);
    cudaFuncSetAttribute(mgemm_k<1>, cudaFuncAttributeMaxDynamicSharedMemorySize, MG_SMEM);
    cudaFuncSetAttribute(mgemm_k<2>, cudaFuncAttributeMaxDynamicSharedMemorySize, MG_SMEM);
    cudaFuncSetAttribute(out_k, cudaFuncAttributeMaxDynamicSharedMemorySize, 64 * 512 * 4);

    __nv_bfloat16 *w1hi, *w1lo, *w2hi, *w2lo, *swhi, *swlo, *ewhi, *ewlo;
    float *relu_p, *x_p, *h_p, *ks_p, *ke_p;
    cudaGetSymbolAddress((void**)&w1hi, g_w1hi);
    cudaGetSymbolAddress((void**)&w1lo, g_w1lo);
    cudaGetSymbolAddress((void**)&w2hi, g_w2hi);
    cudaGetSymbolAddress((void**)&w2lo, g_w2lo);
    cudaGetSymbolAddress((void**)&swhi, g_swhi);
    cudaGetSymbolAddress((void**)&swlo, g_swlo);
    cudaGetSymbolAddress((void**)&ewhi, g_ewhi);
    cudaGetSymbolAddress((void**)&ewlo, g_ewlo);
    cudaGetSymbolAddress((void**)&relu_p, g_relu);
    cudaGetSymbolAddress((void**)&x_p, g_x);
    cudaGetSymbolAddress((void**)&h_p, g_h);
    cudaGetSymbolAddress((void**)&ks_p, g_ks);
    cudaGetSymbolAddress((void**)&ke_p, g_ke);

    wsplit_k<<<dim3(1024 / 32, 512 / 32), 256>>>(ff_w1, w1hi, w1lo, 512, 1024);
    wsplit_k<<<dim3(512 / 32, 1024 / 32), 256>>>(ff_w2, w2hi, w2lo, 1024, 512);
    wsplit_k<<<dim3(256 / 32, 512 / 32), 256>>>(sem_w, swhi, swlo, 512, 256);
    wsplit_k<<<dim3(256 / 32, 512 / 32), 256>>>(epi_w, ewhi, ewlo, 512, 256);

    mgemm_k<0><<<dim3(8, 512), 256, MG_SMEM>>>(seq, embed, nullptr, w1hi, w1lo,
                                               ff_b1, relu_p, 512, 1024);
    mgemm_k<1><<<dim3(4, 512), 256, MG_SMEM>>>(seq, embed, relu_p, w2hi, w2lo,
                                               ff_b2, x_p, 1024, 512);
    ln_k<<<Mz / 8, 256>>>(ln_g, ln_b);
    mgemm_k<2><<<dim3(2, 512), 256, MG_SMEM>>>(seq, embed, h_p, swhi, swlo,
                                               sem_b, ks_p, 512, 256);
    mgemm_k<2><<<dim3(2, 512), 256, MG_SMEM>>>(seq, embed, h_p, ewhi, ewlo,
                                               epi_b, ke_p, 512, 256);
    gram_k<<<dim3(NCH, 2, Bz), 256>>>();
    scan_k<<<dim3(4, 2, Bz), 256, SCAN_SMEM>>>();
    out_k<<<125, 256, 64 * 512 * 4>>>(out_w, out_b, out);
}